// round 16
// baseline (speedup 1.0000x reference)
#include <cuda_runtime.h>
#include <math.h>

#define BB 4
#define SS 2048
#define DD 1024
#define BD (BB*DD)          // 4096
#define MT (BB*SS)          // 8192
#define CH 128
#define NC (SS/CH)          // 16

#define RPB 32              // CTAs per batch group (4 groups x 32 = 128 CTAs)
#define RROW 32             // rows per CTA

typedef unsigned long long ull;

// ------------------------- scratch (device globals; no allocation) ---------
__device__ float g_inp[(size_t)MT*DD];
__device__ float g_gl [(size_t)MT*DD];
__device__ float g_ct [(size_t)MT*DD];
__device__ float g_chend[BD*NC];
__device__ float g_blend[BB*2*DD];
__device__ unsigned g_bar4[BB*32];
// tf32 hi/lo planes (tf32 values in fp32 containers)
__device__ float g_reth[(size_t)MT*DD];
__device__ float g_retl[(size_t)MT*DD];
__device__ float g_inph[(size_t)MT*DD];
__device__ float g_inpl[(size_t)MT*DD];
__device__ float g_sth [(size_t)MT*DD];
__device__ float g_stl [(size_t)MT*DD];
__device__ float g_Wh[(size_t)4*DD*DD];   // 0=Wi 1=Wg 2=Bm 3=Wo
__device__ float g_Wl[(size_t)4*DD*DD];

// ------------------------- helpers ------------------------------------------
__device__ __forceinline__ void cp_async16(unsigned dst, const void* src) {
    asm volatile("cp.async.cg.shared.global [%0], [%1], 16;" :: "r"(dst), "l"(src));
}
#define CP_COMMIT() asm volatile("cp.async.commit_group;")
#define CP_WAIT1()  asm volatile("cp.async.wait_group 1;")
#define CP_WAIT0()  asm volatile("cp.async.wait_group 0;")

__device__ __forceinline__ unsigned f2tf32(float x) {
    unsigned u; asm("cvt.rna.tf32.f32 %0, %1;" : "=r"(u) : "f"(x)); return u;
}
__device__ __forceinline__ void mma_tf32(float* c, const unsigned* a, const unsigned* b) {
    asm volatile(
        "mma.sync.aligned.m16n8k8.row.col.f32.tf32.tf32.f32 "
        "{%0,%1,%2,%3}, {%4,%5,%6,%7}, {%8,%9}, {%0,%1,%2,%3};"
        : "+f"(c[0]), "+f"(c[1]), "+f"(c[2]), "+f"(c[3])
        : "r"(a[0]), "r"(a[1]), "r"(a[2]), "r"(a[3]), "r"(b[0]), "r"(b[1]));
}
__device__ __forceinline__ void ffma2(ull& d, ull a, ull b) {
    asm volatile("fma.rn.f32x2 %0, %1, %2, %0;" : "+l"(d) : "l"(a), "l"(b));
}
__device__ __forceinline__ float2 unpack2(ull v) {
    float2 f; asm("mov.b64 {%0, %1}, %2;" : "=f"(f.x), "=f"(f.y) : "l"(v)); return f;
}
__device__ __forceinline__ float fsigmoid(float x) {
    return __fdividef(1.f, 1.f + __expf(-x));
}
__device__ __forceinline__ float ftanh(float x) {
    x = fminf(fmaxf(x, -15.f), 15.f);
    float e = __expf(2.f * x);
    return __fdividef(e - 1.f, e + 1.f);
}
__device__ __forceinline__ void red_release_add(unsigned* p, unsigned v) {
    asm volatile("red.release.gpu.global.add.u32 [%0], %1;" :: "l"(p), "r"(v) : "memory");
}

// ------------------------- scan pass 1 + weight split + bar reset -----------
// blocks [0,256): chunk-end scan.  blocks [256,1280): weight tf32 splitting.
__global__ void k_scan1(const float* __restrict__ k, const float* __restrict__ v,
                        const float* __restrict__ decay,
                        const float* __restrict__ Wi, const float* __restrict__ Wg,
                        const float* __restrict__ Bm, const float* __restrict__ Wo)
{
    if (blockIdx.x == 0 && threadIdx.x < BB*32) g_bar4[threadIdx.x] = 0u;
    if (blockIdx.x < 256) {
        int g = blockIdx.x * blockDim.x + threadIdx.x;
        int d    = g & (DD-1);
        int rest = g >> 10;
        int ch   = rest & (NC-1);
        int b    = rest >> 4;
        float dec = decay[d >> 6];
        size_t base = ((size_t)(b*SS + ch*CH))*DD + d;
        float r = 0.f;
#pragma unroll 4
        for (int t = 0; t < CH; t++) {
            r = dec*r + k[base + (size_t)t*DD] * v[base + (size_t)t*DD];
        }
        g_chend[(b*NC + ch)*DD + d] = r;
    } else {
        int gtid = (blockIdx.x - 256) * 256 + threadIdx.x;   // 0..262143
#pragma unroll
        for (int j = 0; j < 16; j++) {
            size_t i = (size_t)gtid + (size_t)j * 262144;    // 0..4M
            int wsel = (int)(i >> 20);
            size_t off = i & ((1u<<20) - 1);
            const float* src = (wsel == 0) ? Wi : (wsel == 1) ? Wg
                             : (wsel == 2) ? Bm : Wo;
            float x = src[off];
            unsigned h = f2tf32(x);
            g_Wh[i] = __uint_as_float(h);
            g_Wl[i] = __uint_as_float(f2tf32(x - __uint_as_float(h)));
        }
    }
}

// ------------------------- scan pass 2+3 fused ------------------------------
// Each thread rebuilds its own chunk carry from chend (<=15 cached loads),
// then does the local scan and writes retained split into tf32 hi/lo planes.
__global__ void k_scan23(const float* __restrict__ q, const float* __restrict__ k,
                         const float* __restrict__ v, const float* __restrict__ decay)
{
    int g = blockIdx.x * blockDim.x + threadIdx.x;
    int d    = g & (DD-1);
    int rest = g >> 10;
    int ch   = rest & (NC-1);
    int b    = rest >> 4;
    float dec = decay[d >> 6];
    float dL = dec;
#pragma unroll
    for (int i = 0; i < 7; i++) dL *= dL;   // dec^128
    float r = 0.f;
    for (int j = 0; j < ch; j++)            // carry-in for this chunk
        r = g_chend[(b*NC + j)*DD + d] + dL * r;

    size_t base = ((size_t)(b*SS + ch*CH))*DD + d;
#pragma unroll 4
    for (int t = 0; t < CH; t++) {
        size_t o = base + (size_t)t*DD;
        r = dec*r + k[o]*v[o];
        float ret = q[o]*r;
        unsigned h = f2tf32(ret);
        g_reth[o] = __uint_as_float(h);
        g_retl[o] = __uint_as_float(f2tf32(ret - __uint_as_float(h)));
    }
}

// ------------------------- tf32 plane GEMM ----------------------------------
// C[M,N] = Act[M,K] @ W[N,K]^T (+bias), operands pre-split into tf32 hi/lo
// planes (NO cvt in the inner loop). K-chunk 8, smem stride 12 floats
// (conflict-free: 12g+tig mod 32 is a permutation). 4 planes x double
// buffer = exactly 48KB static smem; 2 CTAs/SM.
#define GS2 12

__global__ __launch_bounds__(256, 2)
void k_gemm(const float* __restrict__ Ah, const float* __restrict__ Al,
            const float* __restrict__ Wh, const float* __restrict__ Wl,
            const float* __restrict__ bias, float* __restrict__ C,
            int hasBias, float* __restrict__ Ch, float* __restrict__ Cl)
{
    __shared__ float As_h[2][128*GS2];
    __shared__ float As_l[2][128*GS2];
    __shared__ float Bs_h[2][128*GS2];
    __shared__ float Bs_l[2][128*GS2];
    int tid  = threadIdx.x;
    int wid  = tid >> 5;
    int lane = tid & 31;
    int g    = lane >> 2;
    int tig  = lane & 3;
    int wm   = wid & 3;
    int wn   = wid >> 2;

    const float* Ahb = Ah + (size_t)blockIdx.y * 128 * DD;
    const float* Alb = Al + (size_t)blockIdx.y * 128 * DD;
    const float* Whb = Wh + (size_t)blockIdx.x * 128 * DD;
    const float* Wlb = Wl + (size_t)blockIdx.x * 128 * DD;
    unsigned sAh = (unsigned)__cvta_generic_to_shared(&As_h[0][0]);
    unsigned sAl = (unsigned)__cvta_generic_to_shared(&As_l[0][0]);
    unsigned sBh = (unsigned)__cvta_generic_to_shared(&Bs_h[0][0]);
    unsigned sBl = (unsigned)__cvta_generic_to_shared(&Bs_l[0][0]);

    float acc[2][8][4];
#pragma unroll
    for (int mt = 0; mt < 2; mt++)
#pragma unroll
        for (int nt = 0; nt < 8; nt++)
#pragma unroll
            for (int i = 0; i < 4; i++) acc[mt][nt][i] = 0.f;

    int lrow = tid >> 1;            // 0..127
    int lc4  = (tid & 1) * 4;       // 0 or 4
    auto loadTile = [&](int buf, int k0) {
        unsigned o = (unsigned)(buf*128*GS2 + lrow*GS2 + lc4) * 4u;
        size_t gsrc = (size_t)lrow*DD + k0 + lc4;
        cp_async16(sAh + o, Ahb + gsrc);
        cp_async16(sAl + o, Alb + gsrc);
        cp_async16(sBh + o, Whb + gsrc);
        cp_async16(sBl + o, Wlb + gsrc);
    };

    const int nk = DD / 8;          // 128
    loadTile(0, 0);
    CP_COMMIT();

    for (int kt = 0; kt < nk; kt++) {
        if (kt + 1 < nk) { loadTile((kt+1) & 1, (kt+1)*8); CP_COMMIT(); CP_WAIT1(); }
        else             { CP_WAIT0(); }
        __syncthreads();

        const float* Ahs = &As_h[kt & 1][0];
        const float* Als = &As_l[kt & 1][0];
        const float* Bhs = &Bs_h[kt & 1][0];
        const float* Bls = &Bs_l[kt & 1][0];

        unsigned ah[2][4], al[2][4];
#pragma unroll
        for (int mt = 0; mt < 2; mt++) {
            int rb = wm*32 + mt*16;
            ah[mt][0] = __float_as_uint(Ahs[(rb + g    )*GS2 + tig    ]);
            ah[mt][1] = __float_as_uint(Ahs[(rb + g + 8)*GS2 + tig    ]);
            ah[mt][2] = __float_as_uint(Ahs[(rb + g    )*GS2 + tig + 4]);
            ah[mt][3] = __float_as_uint(Ahs[(rb + g + 8)*GS2 + tig + 4]);
            al[mt][0] = __float_as_uint(Als[(rb + g    )*GS2 + tig    ]);
            al[mt][1] = __float_as_uint(Als[(rb + g + 8)*GS2 + tig    ]);
            al[mt][2] = __float_as_uint(Als[(rb + g    )*GS2 + tig + 4]);
            al[mt][3] = __float_as_uint(Als[(rb + g + 8)*GS2 + tig + 4]);
        }
        unsigned bh[8][2], bl[8][2];
#pragma unroll
        for (int nt = 0; nt < 8; nt++) {
            int nb = wn*64 + nt*8;
            bh[nt][0] = __float_as_uint(Bhs[(nb + g)*GS2 + tig    ]);
            bh[nt][1] = __float_as_uint(Bhs[(nb + g)*GS2 + tig + 4]);
            bl[nt][0] = __float_as_uint(Bls[(nb + g)*GS2 + tig    ]);
            bl[nt][1] = __float_as_uint(Bls[(nb + g)*GS2 + tig + 4]);
        }
#pragma unroll
        for (int mt = 0; mt < 2; mt++)
#pragma unroll
            for (int nt = 0; nt < 8; nt++) {
                mma_tf32(acc[mt][nt], ah[mt], bh[nt]);
                mma_tf32(acc[mt][nt], ah[mt], bl[nt]);
                mma_tf32(acc[mt][nt], al[mt], bh[nt]);
            }
        __syncthreads();
    }

    // epilogue (+ optional tf32 split of the result)
#pragma unroll
    for (int mt = 0; mt < 2; mt++) {
        int r0 = blockIdx.y*128 + wm*32 + mt*16 + g;
#pragma unroll
        for (int nt = 0; nt < 8; nt++) {
            int c0 = blockIdx.x*128 + wn*64 + nt*8 + 2*tig;
            float b0 = hasBias ? bias[c0]     : 0.f;
            float b1 = hasBias ? bias[c0 + 1] : 0.f;
            float v00 = acc[mt][nt][0] + b0, v01 = acc[mt][nt][1] + b1;
            float v10 = acc[mt][nt][2] + b0, v11 = acc[mt][nt][3] + b1;
            *(float2*)(C + (size_t)r0      *DD + c0) = make_float2(v00, v01);
            *(float2*)(C + (size_t)(r0 + 8)*DD + c0) = make_float2(v10, v11);
            if (Ch) {
                unsigned h00 = f2tf32(v00), h01 = f2tf32(v01);
                unsigned h10 = f2tf32(v10), h11 = f2tf32(v11);
                *(float2*)(Ch + (size_t)r0      *DD + c0) =
                    make_float2(__uint_as_float(h00), __uint_as_float(h01));
                *(float2*)(Ch + (size_t)(r0 + 8)*DD + c0) =
                    make_float2(__uint_as_float(h10), __uint_as_float(h11));
                *(float2*)(Cl + (size_t)r0      *DD + c0) = make_float2(
                    __uint_as_float(f2tf32(v00 - __uint_as_float(h00))),
                    __uint_as_float(f2tf32(v01 - __uint_as_float(h01))));
                *(float2*)(Cl + (size_t)(r0 + 8)*DD + c0) = make_float2(
                    __uint_as_float(f2tf32(v10 - __uint_as_float(h10))),
                    __uint_as_float(f2tf32(v11 - __uint_as_float(h11))));
            }
        }
    }
}

// ------------------------- sequential state recurrence ----------------------
// R13 kernel (frozen structure); phase 4 now writes the state's tf32 hi/lo
// planes directly (consumed by the final GEMM) instead of fp32 state.
__global__ __launch_bounds__(512, 1)
void k_recur(const float* __restrict__ Amat)
{
    __shared__ float bl_s[1040];
    __shared__ float part[16][32];

    int tid   = threadIdx.x;
    int cta   = blockIdx.x;
    int batch = cta >> 5;
    int row0  = (cta & 31) * RROW;
    int w     = tid >> 5;
    int lane  = tid & 31;

    ull a2[32];
    {
        const ulonglong2* Ar =
            (const ulonglong2*)(Amat + (size_t)(row0 + lane)*DD + w*64);
#pragma unroll
        for (int i = 0; i < 16; i++) {
            ulonglong2 u = Ar[i];
            a2[2*i]   = u.x;
            a2[2*i+1] = u.y;
        }
    }

    size_t idx0 = ((size_t)batch*SS)*DD + row0 + lane;
    unsigned* bar = &g_bar4[batch*32];
    float* gb0 = &g_blend[(batch*2    )*DD];
    float* gb1 = &g_blend[(batch*2 + 1)*DD];

    float state = 0.f, gate = 0.f;
    float inp_use = 0.f, ct_use = 0.f;
    float gl_nxt = 0.f, inp_nxt = 0.f, ct_nxt = 0.f;
    if (tid < 32) {
        float gl0 = g_gl[idx0];
        inp_use = g_inp[idx0];
        ct_use  = g_ct [idx0];
        gl_nxt  = g_gl [idx0 + DD];
        inp_nxt = g_inp[idx0 + DD];
        ct_nxt  = g_ct [idx0 + DD];
        gate    = fsigmoid(gl0);
    }
    __syncthreads();

    for (int t = 0; t < SS; t++) {
        float* gb = (t & 1) ? gb1 : gb0;
        float gl_new = 0.f, inp_new = 0.f, ct_new = 0.f;

        if (tid < 32) {
            float bl = fmaf(gate, state - inp_use, inp_use);
            __stcg(&gb[row0 + lane], bl);
            __syncwarp();
            if (lane == 0) red_release_add(bar, 1u);
            int t2 = (t + 2 < SS) ? t + 2 : SS - 1;
            size_t nidx = idx0 + (size_t)t2*DD;
            gl_new  = g_gl [nidx];
            inp_new = g_inp[nidx];
            ct_new  = g_ct [nidx];
            if (lane == 0) {
                unsigned target = (unsigned)(t + 1) * RPB;
                while (*(volatile unsigned*)bar < target) { }
                __threadfence();
            }
            __syncwarp();
        }
        __syncthreads();   // syncA

        if (lane < 16) {
            float4 vv = __ldcg((const float4*)gb + w*16 + lane);
            *(float4*)&bl_s[w*64 + lane*4] = vv;
        }
        __syncwarp();

        {
            const ulonglong2* xb = (const ulonglong2*)&bl_s[w*64];
            ull s0 = 0ull, s1 = 0ull;
#pragma unroll
            for (int i = 0; i < 16; i++) {
                ulonglong2 x = xb[i];
                ffma2(s0, a2[2*i],   x.x);
                ffma2(s1, a2[2*i+1], x.y);
            }
            float2 p0 = unpack2(s0), p1 = unpack2(s1);
            part[w][lane] = (p0.x + p0.y) + (p1.x + p1.y);
        }
        __syncthreads();   // syncC

        if (tid < 32) {
            float s = ct_use;
#pragma unroll
            for (int ww = 0; ww < 16; ww++) s += part[ww][lane];
            state = ftanh(s);
            unsigned h = f2tf32(state);
            size_t so = idx0 + (size_t)t*DD;
            __stcg(&g_sth[so], __uint_as_float(h));
            __stcg(&g_stl[so], __uint_as_float(f2tf32(state - __uint_as_float(h))));
            gate    = fsigmoid(gl_nxt);
            inp_use = inp_nxt;
            ct_use  = ct_nxt;
            gl_nxt  = gl_new;
            inp_nxt = inp_new;
            ct_nxt  = ct_new;
        }
    }
}

// ------------------------- launch -------------------------------------------
extern "C" void kernel_launch(void* const* d_in, const int* in_sizes, int n_in,
                              void* d_out, int out_size)
{
    const float* q     = (const float*)d_in[0];
    const float* k     = (const float*)d_in[1];
    const float* v     = (const float*)d_in[2];
    const float* Wi    = (const float*)d_in[3];
    const float* bi    = (const float*)d_in[4];
    const float* Wg    = (const float*)d_in[5];
    const float* bg    = (const float*)d_in[6];
    const float* A     = (const float*)d_in[7];
    const float* Bm    = (const float*)d_in[8];
    const float* Wo    = (const float*)d_in[9];
    const float* bo    = (const float*)d_in[10];
    const float* decay = (const float*)d_in[11];
    float* out = (float*)d_out;

    void *p_inp, *p_gl, *p_ct;
    void *p_reth, *p_retl, *p_inph, *p_inpl, *p_sth, *p_stl, *p_Wh, *p_Wl;
    cudaGetSymbolAddress(&p_inp,  g_inp);
    cudaGetSymbolAddress(&p_gl,   g_gl);
    cudaGetSymbolAddress(&p_ct,   g_ct);
    cudaGetSymbolAddress(&p_reth, g_reth);
    cudaGetSymbolAddress(&p_retl, g_retl);
    cudaGetSymbolAddress(&p_inph, g_inph);
    cudaGetSymbolAddress(&p_inpl, g_inpl);
    cudaGetSymbolAddress(&p_sth,  g_sth);
    cudaGetSymbolAddress(&p_stl,  g_stl);
    cudaGetSymbolAddress(&p_Wh,   g_Wh);
    cudaGetSymbolAddress(&p_Wl,   g_Wl);
    const float* Wh = (const float*)p_Wh;
    const float* Wl = (const float*)p_Wl;
    const size_t WSZ = (size_t)DD*DD;

    // launch 1: scan pass1 + weight split + bar reset
    k_scan1<<<256 + 1024, 256>>>(k, v, decay, Wi, Wg, Bm, Wo);
    // launch 2: scan pass2+3 fused, writes ret hi/lo planes
    k_scan23<<<(BD*NC)/256, 256>>>(q, k, v, decay);

    dim3 gg(DD/128, MT/128);
    // launch 3: inp = ret @ Wi^T + bi   (writes fp32 + hi/lo planes)
    k_gemm<<<gg, 256>>>((const float*)p_reth, (const float*)p_retl,
                        Wh + 0*WSZ, Wl + 0*WSZ, bi, (float*)p_inp, 1,
                        (float*)p_inph, (float*)p_inpl);
    // launch 4: gl = inp @ Wg^T + bg
    k_gemm<<<gg, 256>>>((const float*)p_inph, (const float*)p_inpl,
                        Wh + 1*WSZ, Wl + 1*WSZ, bg, (float*)p_gl, 1,
                        (float*)0, (float*)0);
    // launch 5: ct = inp @ Bm^T
    k_gemm<<<gg, 256>>>((const float*)p_inph, (const float*)p_inpl,
                        Wh + 2*WSZ, Wl + 2*WSZ, (const float*)0, (float*)p_ct, 0,
                        (float*)0, (float*)0);

    // launch 6: recurrence (ncu -s 5 -c 1 captures THIS next round)
    k_recur<<<BB*RPB, 512>>>(A);

    // launch 7: out = st @ Wo^T + bo
    k_gemm<<<gg, 256>>>((const float*)p_sth, (const float*)p_stl,
                        Wh + 3*WSZ, Wl + 3*WSZ, bo, out, 1,
                        (float*)0, (float*)0);
}